// round 15
// baseline (speedup 1.0000x reference)
#include <cuda_runtime.h>
#include <cuda_fp16.h>
#include <cstdint>

#define DI __device__ __forceinline__

// ---------------- scratch (device globals; no allocation allowed) ----------
__device__ __half g_t1h[192 * 192];            // t1 fp16 row-major [192][192]
__device__ __half g_c2h[192 * 12288];          // core2 fp16 pairs [kp][n][2]
__device__ __half g_t2h[6144 * 384];           // t2 fp16, row-major [6144][384]
__device__ __half g_c3h[384 * 384];            // core3 fp16 pairs [kp][n][2]
__device__ float  g_t3[192 * 768 * 16];
__device__ __half g_Mh[768 * 3072];            // [kp=k/2][n][2] fp16 pairs
__device__ __half g_Xh[32768UL * 768];         // X fp16, plain [row][k]

static constexpr size_t XQ_TOTAL = 32768UL * 768 / 4;   // 6,291,456 float4 quads
static constexpr size_t XQ_HALF  = XQ_TOTAL / 2;
static constexpr int    PRE_BLKS = 1536;                // prepass blocks per mid kernel

// ---------------- helpers ---------------------------------------------------
DI uint32_t smem_u32(const void* p) {
    uint32_t a;
    asm("{ .reg .u64 t; cvta.to.shared.u64 t, %1; cvt.u32.u64 %0, t; }" : "=r"(a) : "l"(p));
    return a;
}
DI void mma_f16(float c[4], const uint32_t a[4], const uint32_t b[2]) {
    asm("mma.sync.aligned.m16n8k16.row.col.f32.f16.f16.f32 "
        "{%0,%1,%2,%3}, {%4,%5,%6,%7}, {%8,%9}, {%0,%1,%2,%3};"
        : "+f"(c[0]), "+f"(c[1]), "+f"(c[2]), "+f"(c[3])
        : "r"(a[0]), "r"(a[1]), "r"(a[2]), "r"(a[3]),
          "r"(b[0]), "r"(b[1]));
}
DI void ldsm_x4(uint32_t r[4], uint32_t addr) {
    asm volatile("ldmatrix.sync.aligned.m8n8.x4.shared.b16 {%0,%1,%2,%3}, [%4];"
        : "=r"(r[0]), "=r"(r[1]), "=r"(r[2]), "=r"(r[3]) : "r"(addr));
}
#define CP16(d, s)  asm volatile("cp.async.cg.shared.global [%0], [%1], 16;" :: "r"(d), "l"(s) : "memory")
#define CP_COMMIT() asm volatile("cp.async.commit_group;" ::: "memory")
#define CP_WAIT1()  asm volatile("cp.async.wait_group 1;" ::: "memory")

// X prepass worker: convert quads [qstart, qstart+qcount) using nb grid-striding blocks
DI void do_pre(const float* __restrict__ X, size_t qstart, size_t qcount,
               int pb, int nb, int tid) {
    for (size_t i = (size_t)pb * 256 + tid; i < qcount; i += (size_t)nb * 256) {
        size_t q = qstart + i;
        float4 v = *(const float4*)(X + q * 4);
        __half2 h0 = __floats2half2_rn(v.x, v.y);
        __half2 h1 = __floats2half2_rn(v.z, v.w);
        *(uint2*)(g_Xh + q * 4) = make_uint2(*(uint32_t*)&h0, *(uint32_t*)&h1);
    }
}

// ---------------- K1: fused t1 + c2h + c3h -----------------------------------
__global__ void k_init(const float* __restrict__ c0, const float* __restrict__ c1,
                       const float* __restrict__ c2, const float* __restrict__ c3) {
    int b = blockIdx.x, tid = threadIdx.x;
    if (b < 144) {
        // t1 = core0 x core1 [192x192], fp16 out
        int idx = b * 256 + tid;
        int p = idx / 192, q = idx % 192;
        int Ii = p >> 4, Oo = p & 15;
        int I = Ii >> 2, i = Ii & 3, O = Oo >> 2, o = Oo & 3;
        float acc = 0.f;
#pragma unroll
        for (int r = 0; r < 12; ++r)
            acc += c0[(I * 4 + O) * 12 + r] * c1[((r * 4 + i) * 4 + o) * 192 + q];
        g_t1h[idx] = __float2half_rn(acc);
    } else if (b < 144 + 576) {
        // core3 -> fp16 pair layout
        int idx = (b - 144) * 256 + tid;
        int k = idx / 384, n = idx % 384;
        g_c3h[((size_t)(k >> 1) * 384 + n) * 2 + (k & 1)] = __float2half_rn(c3[idx]);
    } else {
        // core2 -> fp16 pair layout
        int idx = (b - 720) * 256 + tid;
        int k = idx / 12288, n = idx % 12288;
        g_c2h[((size_t)(k >> 1) * 12288 + n) * 2 + (k & 1)] = __float2half_rn(c2[idx]);
    }
}

// ---------------- mid0 fp16 mma + X-prepass half 1 ---------------------------
// compute blocks: 144 (M=192 BM64, N=12288 BN256, K=192 BK64)
static constexpr int M0_A_ROW = 144;
static constexpr int M0_A_STG = 64 * M0_A_ROW;        // 9216
static constexpr int M0_B_REG = 1056;
static constexpr int M0_B_STG = 32 * M0_B_REG;        // 33792
static constexpr int M0_STG   = M0_A_STG + M0_B_STG;  // 43008
static constexpr int M0_SMEM  = 3 * M0_STG;           // 129024

__global__ __launch_bounds__(256, 1)
void gemm_mid0h(const float* __restrict__ X) {
    int tid = threadIdx.x;
    if (blockIdx.x >= 144) {
        do_pre(X, 0, XQ_HALF, blockIdx.x - 144, PRE_BLKS, tid);
        return;
    }
    extern __shared__ char smem[];
    uint32_t sb = smem_u32(smem);
    int warp = tid >> 5, lane = tid & 31;
    int wm = warp >> 2, wn = warp & 3;          // 2 x 4 warp grid
    int g  = lane >> 2, tg = lane & 3;
    int col0 = (blockIdx.x % 48) * 256;
    int row0 = (blockIdx.x / 48) * 64;

    float c[2][8][4] = {};

    int aRow = tid >> 2, aCp = tid & 3;
    const __half* aSrc = g_t1h + (size_t)(row0 + aRow) * 192 + aCp * 16;
    uint32_t aD0 = (uint32_t)(aRow * M0_A_ROW + aCp * 32);
    const __half* bSrc = g_c2h + (size_t)col0 * 2;

    uint32_t aLane = (uint32_t)((wm * 32 + (lane & 15)) * M0_A_ROW + (lane >> 4) * 16);

#pragma unroll
    for (int t = 0; t < 2; ++t) {
        uint32_t base = sb + t * M0_STG;
        CP16(base + aD0,      aSrc + t * 64);
        CP16(base + aD0 + 16, aSrc + t * 64 + 8);
#pragma unroll
        for (int i = 0; i < 8; ++i) {
            int q = tid + i * 256, r = q >> 6, n4 = (q & 63) * 4;
            CP16(base + M0_A_STG + (uint32_t)(r * M0_B_REG + n4 * 4),
                 bSrc + ((size_t)(t * 32 + r) * 12288 + n4) * 2);
        }
        CP_COMMIT();
    }

    int s = 0;
    for (int t = 0; t < 3; ++t) {
        CP_WAIT1();
        __syncthreads();
        if (t + 2 < 3) {
            int tn = t + 2;
            int sn = s + 2; if (sn >= 3) sn -= 3;
            uint32_t base = sb + sn * M0_STG;
            CP16(base + aD0,      aSrc + tn * 64);
            CP16(base + aD0 + 16, aSrc + tn * 64 + 8);
#pragma unroll
            for (int i = 0; i < 8; ++i) {
                int q = tid + i * 256, r = q >> 6, n4 = (q & 63) * 4;
                CP16(base + M0_A_STG + (uint32_t)(r * M0_B_REG + n4 * 4),
                     bSrc + ((size_t)(tn * 32 + r) * 12288 + n4) * 2);
            }
        }
        CP_COMMIT();

        uint32_t abase = sb + s * M0_STG + aLane;
        const char* B = smem + s * M0_STG + M0_A_STG;

        uint32_t af[2][2][4], bf[2][8][2];
#pragma unroll
        for (int mf = 0; mf < 2; ++mf)
            ldsm_x4(af[0][mf], abase + mf * (16 * M0_A_ROW));
#pragma unroll
        for (int nf = 0; nf < 8; ++nf) {
            int n = wn * 64 + nf * 8 + g;
            bf[0][nf][0] = *(const uint32_t*)(B + tg * M0_B_REG + n * 4);
            bf[0][nf][1] = *(const uint32_t*)(B + (4 + tg) * M0_B_REG + n * 4);
        }
#pragma unroll
        for (int kg = 0; kg < 4; ++kg) {
            int cur = kg & 1, nxt = cur ^ 1;
            if (kg < 3) {
#pragma unroll
                for (int mf = 0; mf < 2; ++mf)
                    ldsm_x4(af[nxt][mf], abase + mf * (16 * M0_A_ROW) + (kg + 1) * 32);
#pragma unroll
                for (int nf = 0; nf < 8; ++nf) {
                    int n = wn * 64 + nf * 8 + g;
                    const char* br = B + (kg + 1) * 8 * M0_B_REG;
                    bf[nxt][nf][0] = *(const uint32_t*)(br + tg * M0_B_REG + n * 4);
                    bf[nxt][nf][1] = *(const uint32_t*)(br + (4 + tg) * M0_B_REG + n * 4);
                }
            }
#pragma unroll
            for (int mf = 0; mf < 2; ++mf)
#pragma unroll
                for (int nf = 0; nf < 8; ++nf)
                    mma_f16(c[mf][nf], af[cur][mf], bf[cur][nf]);
        }
        ++s; if (s == 3) s = 0;
    }

    // fused t2 reindex store
#pragma unroll
    for (int nf = 0; nf < 8; ++nf) {
#pragma unroll
        for (int e2 = 0; e2 < 2; ++e2) {
            int cc = col0 + wn * 64 + nf * 8 + tg * 2 + e2;
            int io = cc / 384, q = cc - io * 384;
            int i = io >> 3, o = io & 7;
#pragma unroll
            for (int mf = 0; mf < 2; ++mf) {
#pragma unroll
                for (int r2 = 0; r2 < 2; ++r2) {
                    int p = row0 + wm * 32 + mf * 16 + g + r2 * 8;
                    int Ii = p >> 4, Oo = p & 15;
                    g_t2h[((size_t)((Ii * 4 + i) * 128 + Oo * 8 + o)) * 384 + q]
                        = __float2half_rn(c[mf][nf][r2 * 2 + e2]);
                }
            }
        }
    }
}

// ---------------- mid1 fp16 mma + X-prepass half 2 ---------------------------
static constexpr int M1_A_ROW = 144;
static constexpr int M1_A_STG = 128 * M1_A_ROW;
static constexpr int M1_B_REG = 528;
static constexpr int M1_B_STG = 32 * M1_B_REG;
static constexpr int M1_STG   = M1_A_STG + M1_B_STG;
static constexpr int M1_SMEM  = 3 * M1_STG;

__global__ __launch_bounds__(256, 1)
void k_mid1h(const float* __restrict__ X) {
    int tid = threadIdx.x;
    if (blockIdx.x >= 144) {
        do_pre(X, XQ_HALF, XQ_TOTAL - XQ_HALF, blockIdx.x - 144, PRE_BLKS, tid);
        return;
    }
    extern __shared__ char smem[];
    uint32_t sb = smem_u32(smem);
    int warp = tid >> 5, lane = tid & 31;
    int wm = warp >> 2, wn = warp & 3;
    int g  = lane >> 2, tg = lane & 3;
    int bn   = (blockIdx.x % 3) * 128;
    int row0 = (blockIdx.x / 3) * 128;

    float c[4][4][4] = {};

    int aRow = tid >> 1, aHalf = tid & 1;
    const __half* aSrc = g_t2h + (size_t)(row0 + aRow) * 384 + aHalf * 32;
    uint32_t aD0 = (uint32_t)(aRow * M1_A_ROW + aHalf * 64);
    const __half* bSrc = g_c3h + (size_t)bn * 2;

    uint32_t aLane = (uint32_t)((wm * 64 + (lane & 15)) * M1_A_ROW + (lane >> 4) * 16);

#pragma unroll
    for (int t = 0; t < 2; ++t) {
        uint32_t base = sb + t * M1_STG;
#pragma unroll
        for (int j = 0; j < 4; ++j)
            CP16(base + aD0 + j * 16, aSrc + t * 64 + j * 8);
#pragma unroll
        for (int i = 0; i < 4; ++i) {
            int q = tid + i * 256, r = q >> 5, n4 = (q & 31) * 4;
            CP16(base + M1_A_STG + (uint32_t)(r * M1_B_REG + n4 * 4),
                 bSrc + ((size_t)(t * 32 + r) * 384 + n4) * 2);
        }
        CP_COMMIT();
    }

    int s = 0;
    for (int t = 0; t < 6; ++t) {
        CP_WAIT1();
        __syncthreads();
        if (t + 2 < 6) {
            int tn = t + 2;
            int sn = s + 2; if (sn >= 3) sn -= 3;
            uint32_t base = sb + sn * M1_STG;
#pragma unroll
            for (int j = 0; j < 4; ++j)
                CP16(base + aD0 + j * 16, aSrc + tn * 64 + j * 8);
#pragma unroll
            for (int i = 0; i < 4; ++i) {
                int q = tid + i * 256, r = q >> 5, n4 = (q & 31) * 4;
                CP16(base + M1_A_STG + (uint32_t)(r * M1_B_REG + n4 * 4),
                     bSrc + ((size_t)(tn * 32 + r) * 384 + n4) * 2);
            }
        }
        CP_COMMIT();

        uint32_t abase = sb + s * M1_STG + aLane;
        const char* B = smem + s * M1_STG + M1_A_STG;

        uint32_t af[2][4][4], bf[2][4][2];
#pragma unroll
        for (int mf = 0; mf < 4; ++mf)
            ldsm_x4(af[0][mf], abase + mf * (16 * M1_A_ROW));
#pragma unroll
        for (int nf = 0; nf < 4; ++nf) {
            int n = wn * 32 + nf * 8 + g;
            bf[0][nf][0] = *(const uint32_t*)(B + tg * M1_B_REG + n * 4);
            bf[0][nf][1] = *(const uint32_t*)(B + (4 + tg) * M1_B_REG + n * 4);
        }
#pragma unroll
        for (int kg = 0; kg < 4; ++kg) {
            int cur = kg & 1, nxt = cur ^ 1;
            if (kg < 3) {
#pragma unroll
                for (int mf = 0; mf < 4; ++mf)
                    ldsm_x4(af[nxt][mf], abase + mf * (16 * M1_A_ROW) + (kg + 1) * 32);
#pragma unroll
                for (int nf = 0; nf < 4; ++nf) {
                    int n = wn * 32 + nf * 8 + g;
                    const char* br = B + (kg + 1) * 8 * M1_B_REG;
                    bf[nxt][nf][0] = *(const uint32_t*)(br + tg * M1_B_REG + n * 4);
                    bf[nxt][nf][1] = *(const uint32_t*)(br + (4 + tg) * M1_B_REG + n * 4);
                }
            }
#pragma unroll
            for (int mf = 0; mf < 4; ++mf)
#pragma unroll
                for (int nf = 0; nf < 4; ++nf)
                    mma_f16(c[mf][nf], af[cur][mf], bf[cur][nf]);
        }
        ++s; if (s == 3) s = 0;
    }

#pragma unroll
    for (int nf = 0; nf < 4; ++nf) {
#pragma unroll
        for (int e2 = 0; e2 < 2; ++e2) {
            int e = bn + wn * 32 + nf * 8 + tg * 2 + e2;
            int gg = e >> 4, q = e & 15;
            int i3 = gg / 6, o3 = gg - 6 * i3;
#pragma unroll
            for (int mf = 0; mf < 4; ++mf) {
#pragma unroll
                for (int r2 = 0; r2 < 2; ++r2) {
                    int r = row0 + wm * 64 + mf * 16 + g + r2 * 8;
                    int Ii2 = r >> 7, Oo2 = r & 127;
                    g_t3[((size_t)((Ii2 * 4 + i3) * 768 + Oo2 * 6 + o3)) * 16 + q]
                        = c[mf][nf][r2 * 2 + e2];
                }
            }
        }
    }
}

// step 4: build M as fp16 pairs g_Mh[(kp*3072 + n)*2 + (k&1)]
__global__ void k_t4(const float* __restrict__ c4) {
    __shared__ float Bs[256];
    int tid = threadIdx.x;
    Bs[tid] = c4[tid];
    __syncthreads();
    int p = blockIdx.x * 256 + tid;
    float a[16];
#pragma unroll
    for (int j = 0; j < 4; ++j) {
        float4 v = *(const float4*)&g_t3[(size_t)p * 16 + j * 4];
        a[j * 4 + 0] = v.x; a[j * 4 + 1] = v.y; a[j * 4 + 2] = v.z; a[j * 4 + 3] = v.w;
    }
    int Ii3 = p / 768, Oo3 = p % 768;
#pragma unroll
    for (int nn = 0; nn < 16; ++nn) {
        float acc = 0.f;
#pragma unroll
        for (int q = 0; q < 16; ++q) acc += a[q] * Bs[q * 16 + nn];
        int i4 = nn >> 2, o4 = nn & 3;
        int k = Ii3 * 4 + i4, n = Oo3 * 4 + o4;
        g_Mh[((size_t)(k >> 1) * 3072 + n) * 2 + (k & 1)] = __float2half_rn(acc);
    }
}

// ---------------- main GEMM (R10 exact): Y = X * M + bias -------------------
static constexpr int A_ROW_B  = 144;
static constexpr int A_STAGE  = 128 * A_ROW_B;        // 18432
static constexpr int B_REG_B  = 1056;
static constexpr int B_STAGE  = 32 * B_REG_B;         // 33792
static constexpr int STAGE    = A_STAGE + B_STAGE;    // 52224
static constexpr int SMEM_MAIN = 3 * STAGE;           // 156672

__global__ __launch_bounds__(256, 1)
void k_main(const float* __restrict__ bias, float* __restrict__ Y) {
    extern __shared__ char smem[];
    uint32_t sb = smem_u32(smem);

    int tid  = threadIdx.x;
    int warp = tid >> 5, lane = tid & 31;
    int wm = warp >> 2, wn = warp & 3;
    int g  = lane >> 2, tg = lane & 3;

    int col0 = blockIdx.x * 256;
    int row0 = blockIdx.y * 128;

    float c[4][8][4] = {};

    int aRow = tid >> 1, aHalf = tid & 1;
    const __half* aSrc = g_Xh + (size_t)(row0 + aRow) * 768 + aHalf * 32;
    uint32_t aD0 = (uint32_t)(aRow * A_ROW_B + aHalf * 64);
    const __half* bSrc = g_Mh + (size_t)col0 * 2;

    uint32_t aLane = (uint32_t)((wm * 64 + (lane & 15)) * A_ROW_B + (lane >> 4) * 16);

#pragma unroll
    for (int t = 0; t < 2; ++t) {
        uint32_t base = sb + t * STAGE;
#pragma unroll
        for (int j = 0; j < 4; ++j)
            CP16(base + aD0 + j * 16, aSrc + t * 64 + j * 8);
#pragma unroll
        for (int i = 0; i < 8; ++i) {
            int q = tid + i * 256, r = q >> 6, n4 = (q & 63) * 4;
            CP16(base + A_STAGE + (uint32_t)(r * B_REG_B + n4 * 4),
                 bSrc + ((size_t)(t * 32 + r) * 3072 + n4) * 2);
        }
        CP_COMMIT();
    }

    int s = 0;
    for (int t = 0; t < 12; ++t) {
        CP_WAIT1();
        __syncthreads();

        if (t + 2 < 12) {
            int tn = t + 2;
            int sn = s + 2; if (sn >= 3) sn -= 3;
            uint32_t base = sb + sn * STAGE;
#pragma unroll
            for (int j = 0; j < 4; ++j)
                CP16(base + aD0 + j * 16, aSrc + tn * 64 + j * 8);
#pragma unroll
            for (int i = 0; i < 8; ++i) {
                int q = tid + i * 256, r = q >> 6, n4 = (q & 63) * 4;
                CP16(base + A_STAGE + (uint32_t)(r * B_REG_B + n4 * 4),
                     bSrc + ((size_t)(tn * 32 + r) * 3072 + n4) * 2);
            }
        }
        CP_COMMIT();

        uint32_t abase = sb + s * STAGE + aLane;
        const char* B = smem + s * STAGE + A_STAGE;

        uint32_t af[2][4][4], bf[2][8][2];
#pragma unroll
        for (int mf = 0; mf < 4; ++mf)
            ldsm_x4(af[0][mf], abase + mf * (16 * A_ROW_B));
#pragma unroll
        for (int nf = 0; nf < 8; ++nf) {
            int n = wn * 64 + nf * 8 + g;
            bf[0][nf][0] = *(const uint32_t*)(B + tg * B_REG_B + n * 4);
            bf[0][nf][1] = *(const uint32_t*)(B + (4 + tg) * B_REG_B + n * 4);
        }

#pragma unroll
        for (int kg = 0; kg < 4; ++kg) {
            int cur = kg & 1, nxt = cur ^ 1;
            if (kg < 3) {
#pragma unroll
                for (int mf = 0; mf < 4; ++mf)
                    ldsm_x4(af[nxt][mf], abase + mf * (16 * A_ROW_B) + (kg + 1) * 32);
#pragma unroll
                for (int nf = 0; nf < 8; ++nf) {
                    int n = wn * 64 + nf * 8 + g;
                    const char* br = B + (kg + 1) * 8 * B_REG_B;
                    bf[nxt][nf][0] = *(const uint32_t*)(br + tg * B_REG_B + n * 4);
                    bf[nxt][nf][1] = *(const uint32_t*)(br + (4 + tg) * B_REG_B + n * 4);
                }
            }
#pragma unroll
            for (int mf = 0; mf < 4; ++mf)
#pragma unroll
                for (int nf = 0; nf < 8; ++nf)
                    mma_f16(c[mf][nf], af[cur][mf], bf[cur][nf]);
        }
        ++s; if (s == 3) s = 0;
    }

    // epilogue: add bias, store
#pragma unroll
    for (int nf = 0; nf < 8; ++nf) {
        int cc = col0 + wn * 64 + nf * 8 + tg * 2;
        float b0 = bias[cc], b1 = bias[cc + 1];
#pragma unroll
        for (int mf = 0; mf < 4; ++mf) {
            int r = row0 + wm * 64 + mf * 16 + g;
            float2 v0 = make_float2(c[mf][nf][0] + b0, c[mf][nf][1] + b1);
            float2 v1 = make_float2(c[mf][nf][2] + b0, c[mf][nf][3] + b1);
            *(float2*)&Y[(size_t)r * 3072 + cc]       = v0;
            *(float2*)&Y[(size_t)(r + 8) * 3072 + cc] = v1;
        }
    }
}

// ---------------- launch -----------------------------------------------------
extern "C" void kernel_launch(void* const* d_in, const int* in_sizes, int n_in,
                              void* d_out, int out_size) {
    const float* x    = (const float*)d_in[0];
    const float* c0   = (const float*)d_in[1];
    const float* c1   = (const float*)d_in[2];
    const float* c2   = (const float*)d_in[3];
    const float* c3   = (const float*)d_in[4];
    const float* c4   = (const float*)d_in[5];
    const float* bias = (const float*)d_in[6];
    float* y = (float*)d_out;

    // K1: t1 + c2h + c3h fused
    k_init<<<144 + 576 + 9216, 256>>>(c0, c1, c2, c3);

    // K2: mid0 GEMM (144 CTAs) + X-prepass half 1 (1536 CTAs)
    cudaFuncSetAttribute(gemm_mid0h, cudaFuncAttributeMaxDynamicSharedMemorySize, M0_SMEM);
    gemm_mid0h<<<144 + PRE_BLKS, 256, M0_SMEM>>>(x);

    // K3: mid1 GEMM (144 CTAs) + X-prepass half 2 (1536 CTAs)
    cudaFuncSetAttribute(k_mid1h, cudaFuncAttributeMaxDynamicSharedMemorySize, M1_SMEM);
    k_mid1h<<<144 + PRE_BLKS, 256, M1_SMEM>>>(x);

    // K4: M -> fp16 pair layout
    k_t4<<<147456 / 256, 256>>>(c4);

    // K5: main GEMM
    cudaFuncSetAttribute(k_main, cudaFuncAttributeMaxDynamicSharedMemorySize, SMEM_MAIN);
    {
        dim3 grid(3072 / 256, 32768 / 128);
        k_main<<<grid, 256, SMEM_MAIN>>>(bias, y);
    }
}

// round 16
// speedup vs baseline: 1.0499x; 1.0499x over previous
#include <cuda_runtime.h>
#include <cuda_fp16.h>
#include <cstdint>

#define DI __device__ __forceinline__

// ---------------- scratch (device globals; no allocation allowed) ----------
__device__ __half g_t1h[192 * 192];            // t1 fp16 row-major [192][192]
__device__ __half g_c2h[192 * 12288];          // core2 fp16 pairs [kp][n][2]
__device__ __half g_t2h[6144 * 384];           // t2 fp16, row-major [6144][384]
__device__ __half g_c3h[384 * 384];            // core3 fp16 pairs [kp][n][2]
__device__ __half g_t3h[192 * 768 * 16];       // t3 fp16
__device__ __half g_Mh[768 * 3072];            // [kp=k/2][n][2] fp16 pairs
__device__ __half g_Xh[32768UL * 768];         // X fp16, plain [row][k]

// ---------------- helpers ---------------------------------------------------
DI uint32_t smem_u32(const void* p) {
    uint32_t a;
    asm("{ .reg .u64 t; cvta.to.shared.u64 t, %1; cvt.u32.u64 %0, t; }" : "=r"(a) : "l"(p));
    return a;
}
DI void mma_f16(float c[4], const uint32_t a[4], const uint32_t b[2]) {
    asm("mma.sync.aligned.m16n8k16.row.col.f32.f16.f16.f32 "
        "{%0,%1,%2,%3}, {%4,%5,%6,%7}, {%8,%9}, {%0,%1,%2,%3};"
        : "+f"(c[0]), "+f"(c[1]), "+f"(c[2]), "+f"(c[3])
        : "r"(a[0]), "r"(a[1]), "r"(a[2]), "r"(a[3]),
          "r"(b[0]), "r"(b[1]));
}
DI void ldsm_x4(uint32_t r[4], uint32_t addr) {
    asm volatile("ldmatrix.sync.aligned.m8n8.x4.shared.b16 {%0,%1,%2,%3}, [%4];"
        : "=r"(r[0]), "=r"(r[1]), "=r"(r[2]), "=r"(r[3]) : "r"(addr));
}
#define CP16(d, s)  asm volatile("cp.async.cg.shared.global [%0], [%1], 16;" :: "r"(d), "l"(s) : "memory")
#define CP_COMMIT() asm volatile("cp.async.commit_group;" ::: "memory")
#define CP_WAIT1()  asm volatile("cp.async.wait_group 1;" ::: "memory")

// ---------------- K1: fused X-prepass + t1 + c3h + c2h (smem-free) ----------
// blocks [0, 24576): X quads; [24576, 24720): t1; [24720, 25296): c3h;
// [25296, 34512): c2h
static constexpr int IB_PRE = 24576;
static constexpr int IB_T1  = IB_PRE + 144;
static constexpr int IB_C3  = IB_T1 + 576;
static constexpr int IB_C2  = IB_C3 + 9216;

__global__ void k_init(const float* __restrict__ c0, const float* __restrict__ c1,
                       const float* __restrict__ c2, const float* __restrict__ c3,
                       const float* __restrict__ X) {
    int b = blockIdx.x, tid = threadIdx.x;
    if (b < IB_PRE) {
        size_t q = (size_t)b * 256 + tid;
        float4 v = *(const float4*)(X + q * 4);
        __half2 h0 = __floats2half2_rn(v.x, v.y);
        __half2 h1 = __floats2half2_rn(v.z, v.w);
        *(uint2*)(g_Xh + q * 4) = make_uint2(*(uint32_t*)&h0, *(uint32_t*)&h1);
    } else if (b < IB_T1) {
        int idx = (b - IB_PRE) * 256 + tid;
        int p = idx / 192, q = idx % 192;
        int Ii = p >> 4, Oo = p & 15;
        int I = Ii >> 2, i = Ii & 3, O = Oo >> 2, o = Oo & 3;
        float acc = 0.f;
#pragma unroll
        for (int r = 0; r < 12; ++r)
            acc += c0[(I * 4 + O) * 12 + r] * c1[((r * 4 + i) * 4 + o) * 192 + q];
        g_t1h[idx] = __float2half_rn(acc);
    } else if (b < IB_C3) {
        int idx = (b - IB_T1) * 256 + tid;
        int k = idx / 384, n = idx % 384;
        g_c3h[((size_t)(k >> 1) * 384 + n) * 2 + (k & 1)] = __float2half_rn(c3[idx]);
    } else {
        int idx = (b - IB_C3) * 256 + tid;
        int k = idx / 12288, n = idx % 12288;
        g_c2h[((size_t)(k >> 1) * 12288 + n) * 2 + (k & 1)] = __float2half_rn(c2[idx]);
    }
}

// ---------------- mid0 fp16 mma: t2 = t1h x c2h, fused t2 reindex ------------
// M=192 (BM64), N=12288 (BN256), K=192 (BK64); 256 thr, 8 warps 2x4, warp 32x64.
static constexpr int M0_A_ROW = 144;
static constexpr int M0_A_STG = 64 * M0_A_ROW;        // 9216
static constexpr int M0_B_REG = 1056;
static constexpr int M0_B_STG = 32 * M0_B_REG;        // 33792
static constexpr int M0_STG   = M0_A_STG + M0_B_STG;  // 43008
static constexpr int M0_SMEM  = 3 * M0_STG;           // 129024

__global__ __launch_bounds__(256, 1)
void gemm_mid0h() {
    extern __shared__ char smem[];
    uint32_t sb = smem_u32(smem);
    int tid  = threadIdx.x;
    int warp = tid >> 5, lane = tid & 31;
    int wm = warp >> 2, wn = warp & 3;          // 2 x 4 warp grid
    int g  = lane >> 2, tg = lane & 3;
    int col0 = blockIdx.x * 256;
    int row0 = blockIdx.y * 64;

    float c[2][8][4] = {};

    int aRow = tid >> 2, aCp = tid & 3;
    const __half* aSrc = g_t1h + (size_t)(row0 + aRow) * 192 + aCp * 16;
    uint32_t aD0 = (uint32_t)(aRow * M0_A_ROW + aCp * 32);
    const __half* bSrc = g_c2h + (size_t)col0 * 2;

    uint32_t aLane = (uint32_t)((wm * 32 + (lane & 15)) * M0_A_ROW + (lane >> 4) * 16);

#pragma unroll
    for (int t = 0; t < 2; ++t) {
        uint32_t base = sb + t * M0_STG;
        CP16(base + aD0,      aSrc + t * 64);
        CP16(base + aD0 + 16, aSrc + t * 64 + 8);
#pragma unroll
        for (int i = 0; i < 8; ++i) {
            int q = tid + i * 256, r = q >> 6, n4 = (q & 63) * 4;
            CP16(base + M0_A_STG + (uint32_t)(r * M0_B_REG + n4 * 4),
                 bSrc + ((size_t)(t * 32 + r) * 12288 + n4) * 2);
        }
        CP_COMMIT();
    }

    int s = 0;
    for (int t = 0; t < 3; ++t) {
        CP_WAIT1();
        __syncthreads();
        if (t + 2 < 3) {
            int tn = t + 2;
            int sn = s + 2; if (sn >= 3) sn -= 3;
            uint32_t base = sb + sn * M0_STG;
            CP16(base + aD0,      aSrc + tn * 64);
            CP16(base + aD0 + 16, aSrc + tn * 64 + 8);
#pragma unroll
            for (int i = 0; i < 8; ++i) {
                int q = tid + i * 256, r = q >> 6, n4 = (q & 63) * 4;
                CP16(base + M0_A_STG + (uint32_t)(r * M0_B_REG + n4 * 4),
                     bSrc + ((size_t)(tn * 32 + r) * 12288 + n4) * 2);
            }
        }
        CP_COMMIT();

        uint32_t abase = sb + s * M0_STG + aLane;
        const char* B = smem + s * M0_STG + M0_A_STG;

        uint32_t af[2][2][4], bf[2][8][2];
#pragma unroll
        for (int mf = 0; mf < 2; ++mf)
            ldsm_x4(af[0][mf], abase + mf * (16 * M0_A_ROW));
#pragma unroll
        for (int nf = 0; nf < 8; ++nf) {
            int n = wn * 64 + nf * 8 + g;
            bf[0][nf][0] = *(const uint32_t*)(B + tg * M0_B_REG + n * 4);
            bf[0][nf][1] = *(const uint32_t*)(B + (4 + tg) * M0_B_REG + n * 4);
        }
#pragma unroll
        for (int kg = 0; kg < 4; ++kg) {
            int cur = kg & 1, nxt = cur ^ 1;
            if (kg < 3) {
#pragma unroll
                for (int mf = 0; mf < 2; ++mf)
                    ldsm_x4(af[nxt][mf], abase + mf * (16 * M0_A_ROW) + (kg + 1) * 32);
#pragma unroll
                for (int nf = 0; nf < 8; ++nf) {
                    int n = wn * 64 + nf * 8 + g;
                    const char* br = B + (kg + 1) * 8 * M0_B_REG;
                    bf[nxt][nf][0] = *(const uint32_t*)(br + tg * M0_B_REG + n * 4);
                    bf[nxt][nf][1] = *(const uint32_t*)(br + (4 + tg) * M0_B_REG + n * 4);
                }
            }
#pragma unroll
            for (int mf = 0; mf < 2; ++mf)
#pragma unroll
                for (int nf = 0; nf < 8; ++nf)
                    mma_f16(c[mf][nf], af[cur][mf], bf[cur][nf]);
        }
        ++s; if (s == 3) s = 0;
    }

    // fused t2 reindex store
#pragma unroll
    for (int nf = 0; nf < 8; ++nf) {
#pragma unroll
        for (int e2 = 0; e2 < 2; ++e2) {
            int cc = col0 + wn * 64 + nf * 8 + tg * 2 + e2;
            int io = cc / 384, q = cc - io * 384;
            int i = io >> 3, o = io & 7;
#pragma unroll
            for (int mf = 0; mf < 2; ++mf) {
#pragma unroll
                for (int r2 = 0; r2 < 2; ++r2) {
                    int p = row0 + wm * 32 + mf * 16 + g + r2 * 8;
                    int Ii = p >> 4, Oo = p & 15;
                    g_t2h[((size_t)((Ii * 4 + i) * 128 + Oo * 8 + o)) * 384 + q]
                        = __float2half_rn(c[mf][nf][r2 * 2 + e2]);
                }
            }
        }
    }
}

// ---------------- mid1 fp16 mma: t3 = t2h x c3h, fused t3 layout (fp16) -----
static constexpr int M1_A_ROW = 144;
static constexpr int M1_A_STG = 128 * M1_A_ROW;
static constexpr int M1_B_REG = 528;
static constexpr int M1_B_STG = 32 * M1_B_REG;
static constexpr int M1_STG   = M1_A_STG + M1_B_STG;
static constexpr int M1_SMEM  = 3 * M1_STG;

__global__ __launch_bounds__(256, 1)
void k_mid1h() {
    extern __shared__ char smem[];
    uint32_t sb = smem_u32(smem);
    int tid  = threadIdx.x;
    int warp = tid >> 5, lane = tid & 31;
    int wm = warp >> 2, wn = warp & 3;
    int g  = lane >> 2, tg = lane & 3;
    int bn   = blockIdx.x * 128;
    int row0 = blockIdx.y * 128;

    float c[4][4][4] = {};

    int aRow = tid >> 1, aHalf = tid & 1;
    const __half* aSrc = g_t2h + (size_t)(row0 + aRow) * 384 + aHalf * 32;
    uint32_t aD0 = (uint32_t)(aRow * M1_A_ROW + aHalf * 64);
    const __half* bSrc = g_c3h + (size_t)bn * 2;

    uint32_t aLane = (uint32_t)((wm * 64 + (lane & 15)) * M1_A_ROW + (lane >> 4) * 16);

#pragma unroll
    for (int t = 0; t < 2; ++t) {
        uint32_t base = sb + t * M1_STG;
#pragma unroll
        for (int j = 0; j < 4; ++j)
            CP16(base + aD0 + j * 16, aSrc + t * 64 + j * 8);
#pragma unroll
        for (int i = 0; i < 4; ++i) {
            int q = tid + i * 256, r = q >> 5, n4 = (q & 31) * 4;
            CP16(base + M1_A_STG + (uint32_t)(r * M1_B_REG + n4 * 4),
                 bSrc + ((size_t)(t * 32 + r) * 384 + n4) * 2);
        }
        CP_COMMIT();
    }

    int s = 0;
    for (int t = 0; t < 6; ++t) {
        CP_WAIT1();
        __syncthreads();
        if (t + 2 < 6) {
            int tn = t + 2;
            int sn = s + 2; if (sn >= 3) sn -= 3;
            uint32_t base = sb + sn * M1_STG;
#pragma unroll
            for (int j = 0; j < 4; ++j)
                CP16(base + aD0 + j * 16, aSrc + tn * 64 + j * 8);
#pragma unroll
            for (int i = 0; i < 4; ++i) {
                int q = tid + i * 256, r = q >> 5, n4 = (q & 31) * 4;
                CP16(base + M1_A_STG + (uint32_t)(r * M1_B_REG + n4 * 4),
                     bSrc + ((size_t)(tn * 32 + r) * 384 + n4) * 2);
            }
        }
        CP_COMMIT();

        uint32_t abase = sb + s * M1_STG + aLane;
        const char* B = smem + s * M1_STG + M1_A_STG;

        uint32_t af[2][4][4], bf[2][4][2];
#pragma unroll
        for (int mf = 0; mf < 4; ++mf)
            ldsm_x4(af[0][mf], abase + mf * (16 * M1_A_ROW));
#pragma unroll
        for (int nf = 0; nf < 4; ++nf) {
            int n = wn * 32 + nf * 8 + g;
            bf[0][nf][0] = *(const uint32_t*)(B + tg * M1_B_REG + n * 4);
            bf[0][nf][1] = *(const uint32_t*)(B + (4 + tg) * M1_B_REG + n * 4);
        }
#pragma unroll
        for (int kg = 0; kg < 4; ++kg) {
            int cur = kg & 1, nxt = cur ^ 1;
            if (kg < 3) {
#pragma unroll
                for (int mf = 0; mf < 4; ++mf)
                    ldsm_x4(af[nxt][mf], abase + mf * (16 * M1_A_ROW) + (kg + 1) * 32);
#pragma unroll
                for (int nf = 0; nf < 4; ++nf) {
                    int n = wn * 32 + nf * 8 + g;
                    const char* br = B + (kg + 1) * 8 * M1_B_REG;
                    bf[nxt][nf][0] = *(const uint32_t*)(br + tg * M1_B_REG + n * 4);
                    bf[nxt][nf][1] = *(const uint32_t*)(br + (4 + tg) * M1_B_REG + n * 4);
                }
            }
#pragma unroll
            for (int mf = 0; mf < 4; ++mf)
#pragma unroll
                for (int nf = 0; nf < 4; ++nf)
                    mma_f16(c[mf][nf], af[cur][mf], bf[cur][nf]);
        }
        ++s; if (s == 3) s = 0;
    }

#pragma unroll
    for (int nf = 0; nf < 4; ++nf) {
#pragma unroll
        for (int e2 = 0; e2 < 2; ++e2) {
            int e = bn + wn * 32 + nf * 8 + tg * 2 + e2;
            int gg = e >> 4, q = e & 15;
            int i3 = gg / 6, o3 = gg - 6 * i3;
#pragma unroll
            for (int mf = 0; mf < 4; ++mf) {
#pragma unroll
                for (int r2 = 0; r2 < 2; ++r2) {
                    int r = row0 + wm * 64 + mf * 16 + g + r2 * 8;
                    int Ii2 = r >> 7, Oo2 = r & 127;
                    g_t3h[((size_t)((Ii2 * 4 + i3) * 768 + Oo2 * 6 + o3)) * 16 + q]
                        = __float2half_rn(c[mf][nf][r2 * 2 + e2]);
                }
            }
        }
    }
}

// step 4: build M as fp16 pairs g_Mh[(kp*3072 + n)*2 + (k&1)], t3 now fp16
__global__ void k_t4(const float* __restrict__ c4) {
    __shared__ float Bs[256];
    int tid = threadIdx.x;
    Bs[tid] = c4[tid];
    __syncthreads();
    int p = blockIdx.x * 256 + tid;
    float a[16];
#pragma unroll
    for (int j = 0; j < 2; ++j) {
        uint4 v = *(const uint4*)&g_t3h[(size_t)p * 16 + j * 8];
        const __half2* h = (const __half2*)&v;
#pragma unroll
        for (int e = 0; e < 4; ++e) {
            float2 f = __half22float2(h[e]);
            a[j * 8 + e * 2 + 0] = f.x;
            a[j * 8 + e * 2 + 1] = f.y;
        }
    }
    int Ii3 = p / 768, Oo3 = p % 768;
#pragma unroll
    for (int nn = 0; nn < 16; ++nn) {
        float acc = 0.f;
#pragma unroll
        for (int q = 0; q < 16; ++q) acc += a[q] * Bs[q * 16 + nn];
        int i4 = nn >> 2, o4 = nn & 3;
        int k = Ii3 * 4 + i4, n = Oo3 * 4 + o4;
        g_Mh[((size_t)(k >> 1) * 3072 + n) * 2 + (k & 1)] = __float2half_rn(acc);
    }
}

// ---------------- main GEMM (R10 exact): Y = X * M + bias -------------------
static constexpr int A_ROW_B  = 144;
static constexpr int A_STAGE  = 128 * A_ROW_B;        // 18432
static constexpr int B_REG_B  = 1056;
static constexpr int B_STAGE  = 32 * B_REG_B;         // 33792
static constexpr int STAGE    = A_STAGE + B_STAGE;    // 52224
static constexpr int SMEM_MAIN = 3 * STAGE;           // 156672

__global__ __launch_bounds__(256, 1)
void k_main(const float* __restrict__ bias, float* __restrict__ Y) {
    extern __shared__ char smem[];
    uint32_t sb = smem_u32(smem);

    int tid  = threadIdx.x;
    int warp = tid >> 5, lane = tid & 31;
    int wm = warp >> 2, wn = warp & 3;
    int g  = lane >> 2, tg = lane & 3;

    int col0 = blockIdx.x * 256;
    int row0 = blockIdx.y * 128;

    float c[4][8][4] = {};

    int aRow = tid >> 1, aHalf = tid & 1;
    const __half* aSrc = g_Xh + (size_t)(row0 + aRow) * 768 + aHalf * 32;
    uint32_t aD0 = (uint32_t)(aRow * A_ROW_B + aHalf * 64);
    const __half* bSrc = g_Mh + (size_t)col0 * 2;

    uint32_t aLane = (uint32_t)((wm * 64 + (lane & 15)) * A_ROW_B + (lane >> 4) * 16);

#pragma unroll
    for (int t = 0; t < 2; ++t) {
        uint32_t base = sb + t * STAGE;
#pragma unroll
        for (int j = 0; j < 4; ++j)
            CP16(base + aD0 + j * 16, aSrc + t * 64 + j * 8);
#pragma unroll
        for (int i = 0; i < 8; ++i) {
            int q = tid + i * 256, r = q >> 6, n4 = (q & 63) * 4;
            CP16(base + A_STAGE + (uint32_t)(r * B_REG_B + n4 * 4),
                 bSrc + ((size_t)(t * 32 + r) * 3072 + n4) * 2);
        }
        CP_COMMIT();
    }

    int s = 0;
    for (int t = 0; t < 12; ++t) {
        CP_WAIT1();
        __syncthreads();

        if (t + 2 < 12) {
            int tn = t + 2;
            int sn = s + 2; if (sn >= 3) sn -= 3;
            uint32_t base = sb + sn * STAGE;
#pragma unroll
            for (int j = 0; j < 4; ++j)
                CP16(base + aD0 + j * 16, aSrc + tn * 64 + j * 8);
#pragma unroll
            for (int i = 0; i < 8; ++i) {
                int q = tid + i * 256, r = q >> 6, n4 = (q & 63) * 4;
                CP16(base + A_STAGE + (uint32_t)(r * B_REG_B + n4 * 4),
                     bSrc + ((size_t)(tn * 32 + r) * 3072 + n4) * 2);
            }
        }
        CP_COMMIT();

        uint32_t abase = sb + s * STAGE + aLane;
        const char* B = smem + s * STAGE + A_STAGE;

        uint32_t af[2][4][4], bf[2][8][2];
#pragma unroll
        for (int mf = 0; mf < 4; ++mf)
            ldsm_x4(af[0][mf], abase + mf * (16 * A_ROW_B));
#pragma unroll
        for (int nf = 0; nf < 8; ++nf) {
            int n = wn * 64 + nf * 8 + g;
            bf[0][nf][0] = *(const uint32_t*)(B + tg * B_REG_B + n * 4);
            bf[0][nf][1] = *(const uint32_t*)(B + (4 + tg) * B_REG_B + n * 4);
        }

#pragma unroll
        for (int kg = 0; kg < 4; ++kg) {
            int cur = kg & 1, nxt = cur ^ 1;
            if (kg < 3) {
#pragma unroll
                for (int mf = 0; mf < 4; ++mf)
                    ldsm_x4(af[nxt][mf], abase + mf * (16 * A_ROW_B) + (kg + 1) * 32);
#pragma unroll
                for (int nf = 0; nf < 8; ++nf) {
                    int n = wn * 64 + nf * 8 + g;
                    const char* br = B + (kg + 1) * 8 * B_REG_B;
                    bf[nxt][nf][0] = *(const uint32_t*)(br + tg * B_REG_B + n * 4);
                    bf[nxt][nf][1] = *(const uint32_t*)(br + (4 + tg) * B_REG_B + n * 4);
                }
            }
#pragma unroll
            for (int mf = 0; mf < 4; ++mf)
#pragma unroll
                for (int nf = 0; nf < 8; ++nf)
                    mma_f16(c[mf][nf], af[cur][mf], bf[cur][nf]);
        }
        ++s; if (s == 3) s = 0;
    }

    // epilogue: add bias, store
#pragma unroll
    for (int nf = 0; nf < 8; ++nf) {
        int cc = col0 + wn * 64 + nf * 8 + tg * 2;
        float b0 = bias[cc], b1 = bias[cc + 1];
#pragma unroll
        for (int mf = 0; mf < 4; ++mf) {
            int r = row0 + wm * 64 + mf * 16 + g;
            float2 v0 = make_float2(c[mf][nf][0] + b0, c[mf][nf][1] + b1);
            float2 v1 = make_float2(c[mf][nf][2] + b0, c[mf][nf][3] + b1);
            *(float2*)&Y[(size_t)r * 3072 + cc]       = v0;
            *(float2*)&Y[(size_t)(r + 8) * 3072 + cc] = v1;
        }
    }
}

// ---------------- launch -----------------------------------------------------
extern "C" void kernel_launch(void* const* d_in, const int* in_sizes, int n_in,
                              void* d_out, int out_size) {
    const float* x    = (const float*)d_in[0];
    const float* c0   = (const float*)d_in[1];
    const float* c1   = (const float*)d_in[2];
    const float* c2   = (const float*)d_in[3];
    const float* c3   = (const float*)d_in[4];
    const float* c4   = (const float*)d_in[5];
    const float* bias = (const float*)d_in[6];
    float* y = (float*)d_out;

    // K1: X-prepass + t1 + c3h + c2h fused (smem-free)
    k_init<<<IB_C2, 256>>>(c0, c1, c2, c3, x);

    // K2: mid0 GEMM
    cudaFuncSetAttribute(gemm_mid0h, cudaFuncAttributeMaxDynamicSharedMemorySize, M0_SMEM);
    {
        dim3 grid(12288 / 256, 192 / 64);
        gemm_mid0h<<<grid, 256, M0_SMEM>>>();
    }

    // K3: mid1 GEMM
    cudaFuncSetAttribute(k_mid1h, cudaFuncAttributeMaxDynamicSharedMemorySize, M1_SMEM);
    {
        dim3 grid(384 / 128, 6144 / 128);
        k_mid1h<<<grid, 256, M1_SMEM>>>();
    }

    // K4: M -> fp16 pair layout
    k_t4<<<147456 / 256, 256>>>(c4);

    // K5: main GEMM
    cudaFuncSetAttribute(k_main, cudaFuncAttributeMaxDynamicSharedMemorySize, SMEM_MAIN);
    {
        dim3 grid(3072 / 256, 32768 / 128);
        k_main<<<grid, 256, SMEM_MAIN>>>(bias, y);
    }
}

// round 17
// speedup vs baseline: 1.0561x; 1.0059x over previous
#include <cuda_runtime.h>
#include <cuda_fp16.h>
#include <cstdint>

#define DI __device__ __forceinline__

// ---------------- scratch (device globals; no allocation allowed) ----------
__device__ __half g_t1h[192 * 192];            // t1 fp16 row-major [192][192]
__device__ __half g_c2h[192 * 12288];          // core2 fp16 pairs [kp][n][2]
__device__ __half g_t2h[6144 * 384];           // t2 fp16, row-major [6144][384]
__device__ __half g_c3h[384 * 384];            // core3 fp16 pairs [kp][n][2]
__device__ __half g_t3h[192 * 768 * 16];       // t3 fp16
__device__ __half g_Mh[768 * 3072];            // [kp=k/2][n][2] fp16 pairs
__device__ __half g_Xh[32768UL * 768];         // X fp16, plain [row][k]

// ---------------- helpers ---------------------------------------------------
DI uint32_t smem_u32(const void* p) {
    uint32_t a;
    asm("{ .reg .u64 t; cvta.to.shared.u64 t, %1; cvt.u32.u64 %0, t; }" : "=r"(a) : "l"(p));
    return a;
}
DI void mma_f16(float c[4], const uint32_t a[4], const uint32_t b[2]) {
    asm("mma.sync.aligned.m16n8k16.row.col.f32.f16.f16.f32 "
        "{%0,%1,%2,%3}, {%4,%5,%6,%7}, {%8,%9}, {%0,%1,%2,%3};"
        : "+f"(c[0]), "+f"(c[1]), "+f"(c[2]), "+f"(c[3])
        : "r"(a[0]), "r"(a[1]), "r"(a[2]), "r"(a[3]),
          "r"(b[0]), "r"(b[1]));
}
DI void ldsm_x4(uint32_t r[4], uint32_t addr) {
    asm volatile("ldmatrix.sync.aligned.m8n8.x4.shared.b16 {%0,%1,%2,%3}, [%4];"
        : "=r"(r[0]), "=r"(r[1]), "=r"(r[2]), "=r"(r[3]) : "r"(addr));
}
#define CP16(d, s)  asm volatile("cp.async.cg.shared.global [%0], [%1], 16;" :: "r"(d), "l"(s) : "memory")
#define CP_COMMIT() asm volatile("cp.async.commit_group;" ::: "memory")
#define CP_WAIT1()  asm volatile("cp.async.wait_group 1;" ::: "memory")

// ---------------- K1: fused X-prepass + t1 + c3h + c2h (smem-free) ----------
static constexpr int IB_PRE = 24576;
static constexpr int IB_T1  = IB_PRE + 144;
static constexpr int IB_C3  = IB_T1 + 576;
static constexpr int IB_C2  = IB_C3 + 9216;

__global__ void k_init(const float* __restrict__ c0, const float* __restrict__ c1,
                       const float* __restrict__ c2, const float* __restrict__ c3,
                       const float* __restrict__ X) {
    int b = blockIdx.x, tid = threadIdx.x;
    if (b < IB_PRE) {
        size_t q = (size_t)b * 256 + tid;
        float4 v = *(const float4*)(X + q * 4);
        __half2 h0 = __floats2half2_rn(v.x, v.y);
        __half2 h1 = __floats2half2_rn(v.z, v.w);
        *(uint2*)(g_Xh + q * 4) = make_uint2(*(uint32_t*)&h0, *(uint32_t*)&h1);
    } else if (b < IB_T1) {
        int idx = (b - IB_PRE) * 256 + tid;
        int p = idx / 192, q = idx % 192;
        int Ii = p >> 4, Oo = p & 15;
        int I = Ii >> 2, i = Ii & 3, O = Oo >> 2, o = Oo & 3;
        float acc = 0.f;
#pragma unroll
        for (int r = 0; r < 12; ++r)
            acc += c0[(I * 4 + O) * 12 + r] * c1[((r * 4 + i) * 4 + o) * 192 + q];
        g_t1h[idx] = __float2half_rn(acc);
    } else if (b < IB_C3) {
        int idx = (b - IB_T1) * 256 + tid;
        int k = idx / 384, n = idx % 384;
        g_c3h[((size_t)(k >> 1) * 384 + n) * 2 + (k & 1)] = __float2half_rn(c3[idx]);
    } else {
        int idx = (b - IB_C3) * 256 + tid;
        int k = idx / 12288, n = idx % 12288;
        g_c2h[((size_t)(k >> 1) * 12288 + n) * 2 + (k & 1)] = __float2half_rn(c2[idx]);
    }
}

// ---------------- mid0 fp16 mma: t2 = t1h x c2h, fused t2 reindex ------------
static constexpr int M0_A_ROW = 144;
static constexpr int M0_A_STG = 64 * M0_A_ROW;        // 9216
static constexpr int M0_B_REG = 1056;
static constexpr int M0_B_STG = 32 * M0_B_REG;        // 33792
static constexpr int M0_STG   = M0_A_STG + M0_B_STG;  // 43008
static constexpr int M0_SMEM  = 3 * M0_STG;           // 129024

__global__ __launch_bounds__(256, 1)
void gemm_mid0h() {
    extern __shared__ char smem[];
    uint32_t sb = smem_u32(smem);
    int tid  = threadIdx.x;
    int warp = tid >> 5, lane = tid & 31;
    int wm = warp >> 2, wn = warp & 3;
    int g  = lane >> 2, tg = lane & 3;
    int col0 = blockIdx.x * 256;
    int row0 = blockIdx.y * 64;

    float c[2][8][4] = {};

    int aRow = tid >> 2, aCp = tid & 3;
    const __half* aSrc = g_t1h + (size_t)(row0 + aRow) * 192 + aCp * 16;
    uint32_t aD0 = (uint32_t)(aRow * M0_A_ROW + aCp * 32);
    const __half* bSrc = g_c2h + (size_t)col0 * 2;

    uint32_t aLane = (uint32_t)((wm * 32 + (lane & 15)) * M0_A_ROW + (lane >> 4) * 16);

#pragma unroll
    for (int t = 0; t < 2; ++t) {
        uint32_t base = sb + t * M0_STG;
        CP16(base + aD0,      aSrc + t * 64);
        CP16(base + aD0 + 16, aSrc + t * 64 + 8);
#pragma unroll
        for (int i = 0; i < 8; ++i) {
            int q = tid + i * 256, r = q >> 6, n4 = (q & 63) * 4;
            CP16(base + M0_A_STG + (uint32_t)(r * M0_B_REG + n4 * 4),
                 bSrc + ((size_t)(t * 32 + r) * 12288 + n4) * 2);
        }
        CP_COMMIT();
    }

    int s = 0;
    for (int t = 0; t < 3; ++t) {
        CP_WAIT1();
        __syncthreads();
        if (t + 2 < 3) {
            int tn = t + 2;
            int sn = s + 2; if (sn >= 3) sn -= 3;
            uint32_t base = sb + sn * M0_STG;
            CP16(base + aD0,      aSrc + tn * 64);
            CP16(base + aD0 + 16, aSrc + tn * 64 + 8);
#pragma unroll
            for (int i = 0; i < 8; ++i) {
                int q = tid + i * 256, r = q >> 6, n4 = (q & 63) * 4;
                CP16(base + M0_A_STG + (uint32_t)(r * M0_B_REG + n4 * 4),
                     bSrc + ((size_t)(tn * 32 + r) * 12288 + n4) * 2);
            }
        }
        CP_COMMIT();

        uint32_t abase = sb + s * M0_STG + aLane;
        const char* B = smem + s * M0_STG + M0_A_STG;

        uint32_t af[2][2][4], bf[2][8][2];
#pragma unroll
        for (int mf = 0; mf < 2; ++mf)
            ldsm_x4(af[0][mf], abase + mf * (16 * M0_A_ROW));
#pragma unroll
        for (int nf = 0; nf < 8; ++nf) {
            int n = wn * 64 + nf * 8 + g;
            bf[0][nf][0] = *(const uint32_t*)(B + tg * M0_B_REG + n * 4);
            bf[0][nf][1] = *(const uint32_t*)(B + (4 + tg) * M0_B_REG + n * 4);
        }
#pragma unroll
        for (int kg = 0; kg < 4; ++kg) {
            int cur = kg & 1, nxt = cur ^ 1;
            if (kg < 3) {
#pragma unroll
                for (int mf = 0; mf < 2; ++mf)
                    ldsm_x4(af[nxt][mf], abase + mf * (16 * M0_A_ROW) + (kg + 1) * 32);
#pragma unroll
                for (int nf = 0; nf < 8; ++nf) {
                    int n = wn * 64 + nf * 8 + g;
                    const char* br = B + (kg + 1) * 8 * M0_B_REG;
                    bf[nxt][nf][0] = *(const uint32_t*)(br + tg * M0_B_REG + n * 4);
                    bf[nxt][nf][1] = *(const uint32_t*)(br + (4 + tg) * M0_B_REG + n * 4);
                }
            }
#pragma unroll
            for (int mf = 0; mf < 2; ++mf)
#pragma unroll
                for (int nf = 0; nf < 8; ++nf)
                    mma_f16(c[mf][nf], af[cur][mf], bf[cur][nf]);
        }
        ++s; if (s == 3) s = 0;
    }

#pragma unroll
    for (int nf = 0; nf < 8; ++nf) {
#pragma unroll
        for (int e2 = 0; e2 < 2; ++e2) {
            int cc = col0 + wn * 64 + nf * 8 + tg * 2 + e2;
            int io = cc / 384, q = cc - io * 384;
            int i = io >> 3, o = io & 7;
#pragma unroll
            for (int mf = 0; mf < 2; ++mf) {
#pragma unroll
                for (int r2 = 0; r2 < 2; ++r2) {
                    int p = row0 + wm * 32 + mf * 16 + g + r2 * 8;
                    int Ii = p >> 4, Oo = p & 15;
                    g_t2h[((size_t)((Ii * 4 + i) * 128 + Oo * 8 + o)) * 384 + q]
                        = __float2half_rn(c[mf][nf][r2 * 2 + e2]);
                }
            }
        }
    }
}

// ---------------- mid1 fp16 mma: t3 = t2h x c3h, fused t3 layout (fp16) -----
static constexpr int M1_A_ROW = 144;
static constexpr int M1_A_STG = 128 * M1_A_ROW;
static constexpr int M1_B_REG = 528;
static constexpr int M1_B_STG = 32 * M1_B_REG;
static constexpr int M1_STG   = M1_A_STG + M1_B_STG;
static constexpr int M1_SMEM  = 3 * M1_STG;

__global__ __launch_bounds__(256, 1)
void k_mid1h() {
    extern __shared__ char smem[];
    uint32_t sb = smem_u32(smem);
    int tid  = threadIdx.x;
    int warp = tid >> 5, lane = tid & 31;
    int wm = warp >> 2, wn = warp & 3;
    int g  = lane >> 2, tg = lane & 3;
    int bn   = blockIdx.x * 128;
    int row0 = blockIdx.y * 128;

    float c[4][4][4] = {};

    int aRow = tid >> 1, aHalf = tid & 1;
    const __half* aSrc = g_t2h + (size_t)(row0 + aRow) * 384 + aHalf * 32;
    uint32_t aD0 = (uint32_t)(aRow * M1_A_ROW + aHalf * 64);
    const __half* bSrc = g_c3h + (size_t)bn * 2;

    uint32_t aLane = (uint32_t)((wm * 64 + (lane & 15)) * M1_A_ROW + (lane >> 4) * 16);

#pragma unroll
    for (int t = 0; t < 2; ++t) {
        uint32_t base = sb + t * M1_STG;
#pragma unroll
        for (int j = 0; j < 4; ++j)
            CP16(base + aD0 + j * 16, aSrc + t * 64 + j * 8);
#pragma unroll
        for (int i = 0; i < 4; ++i) {
            int q = tid + i * 256, r = q >> 5, n4 = (q & 31) * 4;
            CP16(base + M1_A_STG + (uint32_t)(r * M1_B_REG + n4 * 4),
                 bSrc + ((size_t)(t * 32 + r) * 384 + n4) * 2);
        }
        CP_COMMIT();
    }

    int s = 0;
    for (int t = 0; t < 6; ++t) {
        CP_WAIT1();
        __syncthreads();
        if (t + 2 < 6) {
            int tn = t + 2;
            int sn = s + 2; if (sn >= 3) sn -= 3;
            uint32_t base = sb + sn * M1_STG;
#pragma unroll
            for (int j = 0; j < 4; ++j)
                CP16(base + aD0 + j * 16, aSrc + tn * 64 + j * 8);
#pragma unroll
            for (int i = 0; i < 4; ++i) {
                int q = tid + i * 256, r = q >> 5, n4 = (q & 31) * 4;
                CP16(base + M1_A_STG + (uint32_t)(r * M1_B_REG + n4 * 4),
                     bSrc + ((size_t)(tn * 32 + r) * 384 + n4) * 2);
            }
        }
        CP_COMMIT();

        uint32_t abase = sb + s * M1_STG + aLane;
        const char* B = smem + s * M1_STG + M1_A_STG;

        uint32_t af[2][4][4], bf[2][4][2];
#pragma unroll
        for (int mf = 0; mf < 4; ++mf)
            ldsm_x4(af[0][mf], abase + mf * (16 * M1_A_ROW));
#pragma unroll
        for (int nf = 0; nf < 4; ++nf) {
            int n = wn * 32 + nf * 8 + g;
            bf[0][nf][0] = *(const uint32_t*)(B + tg * M1_B_REG + n * 4);
            bf[0][nf][1] = *(const uint32_t*)(B + (4 + tg) * M1_B_REG + n * 4);
        }
#pragma unroll
        for (int kg = 0; kg < 4; ++kg) {
            int cur = kg & 1, nxt = cur ^ 1;
            if (kg < 3) {
#pragma unroll
                for (int mf = 0; mf < 4; ++mf)
                    ldsm_x4(af[nxt][mf], abase + mf * (16 * M1_A_ROW) + (kg + 1) * 32);
#pragma unroll
                for (int nf = 0; nf < 4; ++nf) {
                    int n = wn * 32 + nf * 8 + g;
                    const char* br = B + (kg + 1) * 8 * M1_B_REG;
                    bf[nxt][nf][0] = *(const uint32_t*)(br + tg * M1_B_REG + n * 4);
                    bf[nxt][nf][1] = *(const uint32_t*)(br + (4 + tg) * M1_B_REG + n * 4);
                }
            }
#pragma unroll
            for (int mf = 0; mf < 4; ++mf)
#pragma unroll
                for (int nf = 0; nf < 4; ++nf)
                    mma_f16(c[mf][nf], af[cur][mf], bf[cur][nf]);
        }
        ++s; if (s == 3) s = 0;
    }

#pragma unroll
    for (int nf = 0; nf < 4; ++nf) {
#pragma unroll
        for (int e2 = 0; e2 < 2; ++e2) {
            int e = bn + wn * 32 + nf * 8 + tg * 2 + e2;
            int gg = e >> 4, q = e & 15;
            int i3 = gg / 6, o3 = gg - 6 * i3;
#pragma unroll
            for (int mf = 0; mf < 4; ++mf) {
#pragma unroll
                for (int r2 = 0; r2 < 2; ++r2) {
                    int r = row0 + wm * 64 + mf * 16 + g + r2 * 8;
                    int Ii2 = r >> 7, Oo2 = r & 127;
                    g_t3h[((size_t)((Ii2 * 4 + i3) * 768 + Oo2 * 6 + o3)) * 16 + q]
                        = __float2half_rn(c[mf][nf][r2 * 2 + e2]);
                }
            }
        }
    }
}

// step 4: M fp16 pairs, fully vectorized (LDS.128 Bs rows, 2x ST.128 out)
__global__ void k_t4(const float* __restrict__ c4) {
    __shared__ float Bs[256];
    int tid = threadIdx.x;
    Bs[tid] = c4[tid];
    __syncthreads();
    int p = blockIdx.x * 256 + tid;

    float a[16];
#pragma unroll
    for (int j = 0; j < 2; ++j) {
        uint4 v = *(const uint4*)&g_t3h[(size_t)p * 16 + j * 8];
        const __half2* h = (const __half2*)&v;
#pragma unroll
        for (int e = 0; e < 4; ++e) {
            float2 f = __half22float2(h[e]);
            a[j * 8 + e * 2 + 0] = f.x;
            a[j * 8 + e * 2 + 1] = f.y;
        }
    }

    float acc[16] = {};
#pragma unroll
    for (int q = 0; q < 16; ++q) {
        float aq = a[q];
#pragma unroll
        for (int c4i = 0; c4i < 4; ++c4i) {
            float4 row = *(const float4*)&Bs[q * 16 + c4i * 4];
            acc[c4i * 4 + 0] += aq * row.x;
            acc[c4i * 4 + 1] += aq * row.y;
            acc[c4i * 4 + 2] += aq * row.z;
            acc[c4i * 4 + 3] += aq * row.w;
        }
    }

    int Ii3 = p / 768, Oo3 = p % 768;
    // acc[nn], nn = i4*4+o4; dest half = (kp*3072 + Oo3*4 + o4)*2 + (i4&1),
    // kp = Ii3*2 + (i4>>1). For each g2=i4>>1: 8 contiguous halves = 1 ST.128.
#pragma unroll
    for (int g2 = 0; g2 < 2; ++g2) {
        int kp = Ii3 * 2 + g2;
        __half2 h[4];
#pragma unroll
        for (int o4 = 0; o4 < 4; ++o4)
            h[o4] = __floats2half2_rn(acc[(g2 * 2 + 0) * 4 + o4],
                                      acc[(g2 * 2 + 1) * 4 + o4]);
        *(uint4*)&g_Mh[((size_t)kp * 3072 + Oo3 * 4) * 2] = *(const uint4*)h;
    }
}

// ---------------- main GEMM (R10 exact): Y = X * M + bias -------------------
static constexpr int A_ROW_B  = 144;
static constexpr int A_STAGE  = 128 * A_ROW_B;        // 18432
static constexpr int B_REG_B  = 1056;
static constexpr int B_STAGE  = 32 * B_REG_B;         // 33792
static constexpr int STAGE    = A_STAGE + B_STAGE;    // 52224
static constexpr int SMEM_MAIN = 3 * STAGE;           // 156672

__global__ __launch_bounds__(256, 1)
void k_main(const float* __restrict__ bias, float* __restrict__ Y) {
    extern __shared__ char smem[];
    uint32_t sb = smem_u32(smem);

    int tid  = threadIdx.x;
    int warp = tid >> 5, lane = tid & 31;
    int wm = warp >> 2, wn = warp & 3;
    int g  = lane >> 2, tg = lane & 3;

    int col0 = blockIdx.x * 256;
    int row0 = blockIdx.y * 128;

    float c[4][8][4] = {};

    int aRow = tid >> 1, aHalf = tid & 1;
    const __half* aSrc = g_Xh + (size_t)(row0 + aRow) * 768 + aHalf * 32;
    uint32_t aD0 = (uint32_t)(aRow * A_ROW_B + aHalf * 64);
    const __half* bSrc = g_Mh + (size_t)col0 * 2;

    uint32_t aLane = (uint32_t)((wm * 64 + (lane & 15)) * A_ROW_B + (lane >> 4) * 16);

#pragma unroll
    for (int t = 0; t < 2; ++t) {
        uint32_t base = sb + t * STAGE;
#pragma unroll
        for (int j = 0; j < 4; ++j)
            CP16(base + aD0 + j * 16, aSrc + t * 64 + j * 8);
#pragma unroll
        for (int i = 0; i < 8; ++i) {
            int q = tid + i * 256, r = q >> 6, n4 = (q & 63) * 4;
            CP16(base + A_STAGE + (uint32_t)(r * B_REG_B + n4 * 4),
                 bSrc + ((size_t)(t * 32 + r) * 3072 + n4) * 2);
        }
        CP_COMMIT();
    }

    int s = 0;
    for (int t = 0; t < 12; ++t) {
        CP_WAIT1();
        __syncthreads();

        if (t + 2 < 12) {
            int tn = t + 2;
            int sn = s + 2; if (sn >= 3) sn -= 3;
            uint32_t base = sb + sn * STAGE;
#pragma unroll
            for (int j = 0; j < 4; ++j)
                CP16(base + aD0 + j * 16, aSrc + tn * 64 + j * 8);
#pragma unroll
            for (int i = 0; i < 8; ++i) {
                int q = tid + i * 256, r = q >> 6, n4 = (q & 63) * 4;
                CP16(base + A_STAGE + (uint32_t)(r * B_REG_B + n4 * 4),
                     bSrc + ((size_t)(tn * 32 + r) * 3072 + n4) * 2);
            }
        }
        CP_COMMIT();

        uint32_t abase = sb + s * STAGE + aLane;
        const char* B = smem + s * STAGE + A_STAGE;

        uint32_t af[2][4][4], bf[2][8][2];
#pragma unroll
        for (int mf = 0; mf < 4; ++mf)
            ldsm_x4(af[0][mf], abase + mf * (16 * A_ROW_B));
#pragma unroll
        for (int nf = 0; nf < 8; ++nf) {
            int n = wn * 64 + nf * 8 + g;
            bf[0][nf][0] = *(const uint32_t*)(B + tg * B_REG_B + n * 4);
            bf[0][nf][1] = *(const uint32_t*)(B + (4 + tg) * B_REG_B + n * 4);
        }

#pragma unroll
        for (int kg = 0; kg < 4; ++kg) {
            int cur = kg & 1, nxt = cur ^ 1;
            if (kg < 3) {
#pragma unroll
                for (int mf = 0; mf < 4; ++mf)
                    ldsm_x4(af[nxt][mf], abase + mf * (16 * A_ROW_B) + (kg + 1) * 32);
#pragma unroll
                for (int nf = 0; nf < 8; ++nf) {
                    int n = wn * 64 + nf * 8 + g;
                    const char* br = B + (kg + 1) * 8 * B_REG_B;
                    bf[nxt][nf][0] = *(const uint32_t*)(br + tg * B_REG_B + n * 4);
                    bf[nxt][nf][1] = *(const uint32_t*)(br + (4 + tg) * B_REG_B + n * 4);
                }
            }
#pragma unroll
            for (int mf = 0; mf < 4; ++mf)
#pragma unroll
                for (int nf = 0; nf < 8; ++nf)
                    mma_f16(c[mf][nf], af[cur][mf], bf[cur][nf]);
        }
        ++s; if (s == 3) s = 0;
    }

    // epilogue: add bias, store
#pragma unroll
    for (int nf = 0; nf < 8; ++nf) {
        int cc = col0 + wn * 64 + nf * 8 + tg * 2;
        float b0 = bias[cc], b1 = bias[cc + 1];
#pragma unroll
        for (int mf = 0; mf < 4; ++mf) {
            int r = row0 + wm * 64 + mf * 16 + g;
            float2 v0 = make_float2(c[mf][nf][0] + b0, c[mf][nf][1] + b1);
            float2 v1 = make_float2(c[mf][nf][2] + b0, c[mf][nf][3] + b1);
            *(float2*)&Y[(size_t)r * 3072 + cc]       = v0;
            *(float2*)&Y[(size_t)(r + 8) * 3072 + cc] = v1;
        }
    }
}

// ---------------- launch -----------------------------------------------------
extern "C" void kernel_launch(void* const* d_in, const int* in_sizes, int n_in,
                              void* d_out, int out_size) {
    const float* x    = (const float*)d_in[0];
    const float* c0   = (const float*)d_in[1];
    const float* c1   = (const float*)d_in[2];
    const float* c2   = (const float*)d_in[3];
    const float* c3   = (const float*)d_in[4];
    const float* c4   = (const float*)d_in[5];
    const float* bias = (const float*)d_in[6];
    float* y = (float*)d_out;

    // K1: X-prepass + t1 + c3h + c2h fused (smem-free)
    k_init<<<IB_C2, 256>>>(c0, c1, c2, c3, x);

    // K2: mid0 GEMM
    cudaFuncSetAttribute(gemm_mid0h, cudaFuncAttributeMaxDynamicSharedMemorySize, M0_SMEM);
    {
        dim3 grid(12288 / 256, 192 / 64);
        gemm_mid0h<<<grid, 256, M0_SMEM>>>();
    }

    // K3: mid1 GEMM
    cudaFuncSetAttribute(k_mid1h, cudaFuncAttributeMaxDynamicSharedMemorySize, M1_SMEM);
    {
        dim3 grid(384 / 128, 6144 / 128);
        k_mid1h<<<grid, 256, M1_SMEM>>>();
    }

    // K4: M -> fp16 pair layout (vectorized)
    k_t4<<<147456 / 256, 256>>>(c4);

    // K5: main GEMM
    cudaFuncSetAttribute(k_main, cudaFuncAttributeMaxDynamicSharedMemorySize, SMEM_MAIN);
    {
        dim3 grid(3072 / 256, 32768 / 128);
        k_main<<<grid, 256, SMEM_MAIN>>>(bias, y);
    }
}